// round 1
// baseline (speedup 1.0000x reference)
#include <cuda_runtime.h>
#include <cuda_bf16.h>
#include <cstdint>

// ---------------- problem constants ----------------
#define USER_NUM 100000
#define ITEM_NUM 50000
#define N_NODES  150000      // USER_NUM + ITEM_NUM
#define REC_DIM  256
#define D4       64          // REC_DIM / 4
#define NNZ      6400000
#define BATCH    16384

// Layer scratch: 3 x 150000 x 256 floats = 3 x 153.6 MB (static device memory
// — allowed; no runtime allocation).
__device__ float g_c1[(size_t)N_NODES * REC_DIM];
__device__ float g_c2[(size_t)N_NODES * REC_DIM];
__device__ float g_c3[(size_t)N_NODES * REC_DIM];

// ---------------- zero kernel ----------------
__global__ void zero_kernel(float4* __restrict__ p, int n4) {
    int i = blockIdx.x * blockDim.x + threadIdx.x;
    if (i < n4) p[i] = make_float4(0.f, 0.f, 0.f, 0.f);
}

// ---------------- SpMM: layer 1 (reads from virtual concat) ----------------
// One warp per edge; lane l handles float4 indices l and l+32.
__global__ void spmm_l1_kernel(const float* __restrict__ user_emb,
                               const float* __restrict__ item_emb,
                               const float* __restrict__ vals,
                               const int*   __restrict__ rows,
                               const int*   __restrict__ cols,
                               float*       __restrict__ next) {
    int e = (blockIdx.x * blockDim.x + threadIdx.x) >> 5;
    if (e >= NNZ) return;
    int lane = threadIdx.x & 31;

    int r = rows[e];
    int c = cols[e];
    float v = vals[e];

    const float4* src;
    if (c < USER_NUM) src = (const float4*)user_emb + (size_t)c * D4;
    else              src = (const float4*)item_emb + (size_t)(c - USER_NUM) * D4;

    float4* dst = (float4*)next + (size_t)r * D4;

#pragma unroll
    for (int j = 0; j < 2; j++) {
        int idx = lane + 32 * j;
        float4 s = src[idx];
        s.x *= v; s.y *= v; s.z *= v; s.w *= v;
        atomicAdd(&dst[idx], s);   // sm_90+ vector float4 atomic
    }
}

// ---------------- SpMM: generic layer (cur -> next) ----------------
__global__ void spmm_kernel(const float* __restrict__ cur,
                            const float* __restrict__ vals,
                            const int*   __restrict__ rows,
                            const int*   __restrict__ cols,
                            float*       __restrict__ next) {
    int e = (blockIdx.x * blockDim.x + threadIdx.x) >> 5;
    if (e >= NNZ) return;
    int lane = threadIdx.x & 31;

    int r = rows[e];
    int c = cols[e];
    float v = vals[e];

    const float4* src = (const float4*)cur + (size_t)c * D4;
    float4*       dst = (float4*)next + (size_t)r * D4;

#pragma unroll
    for (int j = 0; j < 2; j++) {
        int idx = lane + 32 * j;
        float4 s = src[idx];
        s.x *= v; s.y *= v; s.z *= v; s.w *= v;
        atomicAdd(&dst[idx], s);
    }
}

// ---------------- final gather + dot ----------------
// One warp per batch element. mean = (c0+c1+c2+c3)/4 on each side -> product
// carries 1/16.
__global__ void gather_dot_kernel(const float* __restrict__ user_emb,
                                  const float* __restrict__ item_emb,
                                  const int*   __restrict__ users,
                                  const int*   __restrict__ items,
                                  const float* __restrict__ c1,
                                  const float* __restrict__ c2,
                                  const float* __restrict__ c3,
                                  float*       __restrict__ out) {
    int w = (blockIdx.x * blockDim.x + threadIdx.x) >> 5;
    if (w >= BATCH) return;
    int lane = threadIdx.x & 31;

    int u  = users[w];
    int it = items[w];
    size_t un = (size_t)u;                  // node index of user
    size_t in_ = (size_t)(USER_NUM + it);   // node index of item

    const float4* u0 = (const float4*)user_emb + (size_t)u * D4;
    const float4* i0 = (const float4*)item_emb + (size_t)it * D4;
    const float4* c1f = (const float4*)c1;
    const float4* c2f = (const float4*)c2;
    const float4* c3f = (const float4*)c3;

    float acc = 0.f;
#pragma unroll
    for (int j = 0; j < 2; j++) {
        int idx = lane + 32 * j;
        float4 a = u0[idx];
        float4 a1 = c1f[un * D4 + idx];
        float4 a2 = c2f[un * D4 + idx];
        float4 a3 = c3f[un * D4 + idx];
        a.x += a1.x + a2.x + a3.x;
        a.y += a1.y + a2.y + a3.y;
        a.z += a1.z + a2.z + a3.z;
        a.w += a1.w + a2.w + a3.w;

        float4 b = i0[idx];
        float4 b1 = c1f[in_ * D4 + idx];
        float4 b2 = c2f[in_ * D4 + idx];
        float4 b3 = c3f[in_ * D4 + idx];
        b.x += b1.x + b2.x + b3.x;
        b.y += b1.y + b2.y + b3.y;
        b.z += b1.z + b2.z + b3.z;
        b.w += b1.w + b2.w + b3.w;

        acc += a.x * b.x + a.y * b.y + a.z * b.z + a.w * b.w;
    }

    // warp reduce
#pragma unroll
    for (int off = 16; off > 0; off >>= 1)
        acc += __shfl_down_sync(0xFFFFFFFFu, acc, off);

    if (lane == 0) out[w] = acc * (1.0f / 16.0f);
}

extern "C" void kernel_launch(void* const* d_in, const int* in_sizes, int n_in,
                              void* d_out, int out_size) {
    const float* user_emb = (const float*)d_in[0];
    const float* item_emb = (const float*)d_in[1];
    const float* vals     = (const float*)d_in[2];
    const int*   rows     = (const int*)d_in[3];
    const int*   cols     = (const int*)d_in[4];
    const int*   users    = (const int*)d_in[5];
    const int*   items    = (const int*)d_in[6];
    float* out = (float*)d_out;

    float* c1; cudaGetSymbolAddress((void**)&c1, g_c1);
    float* c2; cudaGetSymbolAddress((void**)&c2, g_c2);
    float* c3; cudaGetSymbolAddress((void**)&c3, g_c3);

    const int n4 = N_NODES * D4;                       // 9.6M float4
    const int zblocks = (n4 + 255) / 256;
    zero_kernel<<<zblocks, 256>>>((float4*)c1, n4);
    zero_kernel<<<zblocks, 256>>>((float4*)c2, n4);
    zero_kernel<<<zblocks, 256>>>((float4*)c3, n4);

    const int spmm_blocks = (NNZ * 32 + 255) / 256;    // warp per edge
    spmm_l1_kernel<<<spmm_blocks, 256>>>(user_emb, item_emb, vals, rows, cols, c1);
    spmm_kernel<<<spmm_blocks, 256>>>(c1, vals, rows, cols, c2);
    spmm_kernel<<<spmm_blocks, 256>>>(c2, vals, rows, cols, c3);

    const int gblocks = (BATCH * 32 + 255) / 256;
    gather_dot_kernel<<<gblocks, 256>>>(user_emb, item_emb, users, items,
                                        c1, c2, c3, out);
}

// round 3
// speedup vs baseline: 5.1640x; 5.1640x over previous
#include <cuda_runtime.h>
#include <cuda_fp16.h>
#include <cstdint>

// ---------------- problem constants ----------------
#define USER_NUM 100000
#define ITEM_NUM 50000
#define N_NODES  150000      // USER_NUM + ITEM_NUM
#define REC_DIM  256
#define D4       64          // REC_DIM / 4 (float4 per row)
#define DH4      32          // REC_DIM / 8 (uint4-of-8-halves per row)
#define NNZ      6400000
#define BATCH    16384
#define SCAN_T   1024
#define SCAN_CH  ((N_NODES + SCAN_T - 1) / SCAN_T)   // 147

// ---------------- static device scratch (no runtime allocation) ----------------
__device__ __half g_h0[(size_t)N_NODES * REC_DIM];   // 76.8 MB each
__device__ __half g_h1[(size_t)N_NODES * REC_DIM];
__device__ __half g_h2[(size_t)N_NODES * REC_DIM];
__device__ __half g_h3[(size_t)N_NODES * REC_DIM];
__device__ int    g_counts[N_NODES];
__device__ int    g_rowptr[N_NODES + 1];
__device__ int    g_fill[N_NODES];
__device__ int2   g_edges[NNZ];                      // {col, val-as-int-bits}

// ---------------- CSR build ----------------
__global__ void zero_counts_kernel(int* __restrict__ counts) {
    int i = blockIdx.x * blockDim.x + threadIdx.x;
    if (i < N_NODES) counts[i] = 0;
}

__global__ void hist_kernel(const int* __restrict__ rows, int* __restrict__ counts) {
    int e = blockIdx.x * blockDim.x + threadIdx.x;
    if (e < NNZ) atomicAdd(&counts[rows[e]], 1);
}

// Single-block exclusive scan over 150000 counts -> row_ptr (and fill copy).
__global__ void scan_kernel(const int* __restrict__ counts,
                            int* __restrict__ row_ptr,
                            int* __restrict__ fill) {
    __shared__ int ssum[SCAN_T];
    int t = threadIdx.x;
    int beg = t * SCAN_CH;
    int end = min(beg + SCAN_CH, N_NODES);
    int s = 0;
    for (int i = beg; i < end; i++) s += counts[i];
    ssum[t] = s;
    __syncthreads();
    // Hillis-Steele inclusive scan over thread sums
    for (int off = 1; off < SCAN_T; off <<= 1) {
        int v = (t >= off) ? ssum[t - off] : 0;
        __syncthreads();
        ssum[t] += v;
        __syncthreads();
    }
    int prefix = (t == 0) ? 0 : ssum[t - 1];
    for (int i = beg; i < end; i++) {
        row_ptr[i] = prefix;
        fill[i] = prefix;
        prefix += counts[i];
    }
    if (t == SCAN_T - 1) row_ptr[N_NODES] = prefix;
}

__global__ void scatter_kernel(const int* __restrict__ rows,
                               const int* __restrict__ cols,
                               const float* __restrict__ vals,
                               int* __restrict__ fill,
                               int2* __restrict__ edges) {
    int e = blockIdx.x * blockDim.x + threadIdx.x;
    if (e >= NNZ) return;
    int r = rows[e];
    int pos = atomicAdd(&fill[r], 1);
    edges[pos] = make_int2(cols[e], __float_as_int(vals[e]));
}

// ---------------- fp32 concat -> fp16 ----------------
__global__ void to_half_kernel(const float* __restrict__ user_emb,
                               const float* __restrict__ item_emb,
                               __half* __restrict__ h0) {
    // one thread = one float4 (4 elements)
    int i = blockIdx.x * blockDim.x + threadIdx.x;   // < N_NODES * D4
    if (i >= N_NODES * D4) return;
    const int user_f4 = USER_NUM * D4;
    float4 f = (i < user_f4) ? ((const float4*)user_emb)[i]
                             : ((const float4*)item_emb)[i - user_f4];
    __half2 lo = __floats2half2_rn(f.x, f.y);
    __half2 hi = __floats2half2_rn(f.z, f.w);
    uint2 o;
    o.x = *(unsigned int*)&lo;
    o.y = *(unsigned int*)&hi;
    ((uint2*)h0)[i] = o;
}

// ---------------- CSR row-gather SpMM (fp16 storage, fp32 accumulate) --------
// One warp per output row. Lane owns 8 features (one uint4 of halves).
__global__ void spmm_csr_kernel(const __half* __restrict__ cur,
                                const int* __restrict__ row_ptr,
                                const int2* __restrict__ edges,
                                __half* __restrict__ next) {
    int r = (blockIdx.x * blockDim.x + threadIdx.x) >> 5;
    if (r >= N_NODES) return;
    int lane = threadIdx.x & 31;

    int start = row_ptr[r];
    int end   = row_ptr[r + 1];

    float acc[8];
#pragma unroll
    for (int k = 0; k < 8; k++) acc[k] = 0.f;

    const uint4* curv = (const uint4*)cur;   // 8 halves each

    int e = start;
    while (e < end) {
        int tile = end - e;
        if (tile > 8) tile = 8;
        int2 ed[8];
#pragma unroll
        for (int i = 0; i < 8; i++)
            if (i < tile) ed[i] = __ldcs(&edges[e + i]);   // streaming
#pragma unroll
        for (int i = 0; i < 8; i++) {
            if (i < tile) {
                int col = ed[i].x;
                float v = __int_as_float(ed[i].y);
                uint4 h = __ldg(&curv[col * DH4 + lane]);  // L2-resident gather
                const __half2* hp = (const __half2*)&h;
#pragma unroll
                for (int k = 0; k < 4; k++) {
                    float2 f = __half22float2(hp[k]);
                    acc[2 * k]     += v * f.x;
                    acc[2 * k + 1] += v * f.y;
                }
            }
        }
        e += tile;
    }

    uint4 o;
    __half2* op = (__half2*)&o;
#pragma unroll
    for (int k = 0; k < 4; k++)
        op[k] = __floats2half2_rn(acc[2 * k], acc[2 * k + 1]);
    __stcs(&((uint4*)next)[r * DH4 + lane], o);            // streaming store
}

// ---------------- final gather + dot ----------------
// One warp per batch element; lane owns 8 features.
__global__ void gather_dot_kernel(const float* __restrict__ user_emb,
                                  const float* __restrict__ item_emb,
                                  const int*   __restrict__ users,
                                  const int*   __restrict__ items,
                                  const __half* __restrict__ h1,
                                  const __half* __restrict__ h2,
                                  const __half* __restrict__ h3,
                                  float*       __restrict__ out) {
    int w = (blockIdx.x * blockDim.x + threadIdx.x) >> 5;
    if (w >= BATCH) return;
    int lane = threadIdx.x & 31;

    int u  = users[w];
    int it = items[w];
    size_t un  = (size_t)u;
    size_t in_ = (size_t)(USER_NUM + it);

    const uint4* h1v = (const uint4*)h1;
    const uint4* h2v = (const uint4*)h2;
    const uint4* h3v = (const uint4*)h3;

    float a[8], b[8];
    // user side: fp32 base emb + 3 half layers
    {
        const float4* p = (const float4*)user_emb + (size_t)u * D4;
        float4 f0 = p[lane * 2], f1 = p[lane * 2 + 1];
        a[0] = f0.x; a[1] = f0.y; a[2] = f0.z; a[3] = f0.w;
        a[4] = f1.x; a[5] = f1.y; a[6] = f1.z; a[7] = f1.w;
        uint4 q1 = h1v[un * DH4 + lane];
        uint4 q2 = h2v[un * DH4 + lane];
        uint4 q3 = h3v[un * DH4 + lane];
        const __half2 *p1 = (const __half2*)&q1, *p2 = (const __half2*)&q2, *p3 = (const __half2*)&q3;
#pragma unroll
        for (int k = 0; k < 4; k++) {
            float2 f_1 = __half22float2(p1[k]);
            float2 f_2 = __half22float2(p2[k]);
            float2 f_3 = __half22float2(p3[k]);
            a[2*k]   += f_1.x + f_2.x + f_3.x;
            a[2*k+1] += f_1.y + f_2.y + f_3.y;
        }
    }
    // item side
    {
        const float4* p = (const float4*)item_emb + (size_t)it * D4;
        float4 f0 = p[lane * 2], f1 = p[lane * 2 + 1];
        b[0] = f0.x; b[1] = f0.y; b[2] = f0.z; b[3] = f0.w;
        b[4] = f1.x; b[5] = f1.y; b[6] = f1.z; b[7] = f1.w;
        uint4 q1 = h1v[in_ * DH4 + lane];
        uint4 q2 = h2v[in_ * DH4 + lane];
        uint4 q3 = h3v[in_ * DH4 + lane];
        const __half2 *p1 = (const __half2*)&q1, *p2 = (const __half2*)&q2, *p3 = (const __half2*)&q3;
#pragma unroll
        for (int k = 0; k < 4; k++) {
            float2 f_1 = __half22float2(p1[k]);
            float2 f_2 = __half22float2(p2[k]);
            float2 f_3 = __half22float2(p3[k]);
            b[2*k]   += f_1.x + f_2.x + f_3.x;
            b[2*k+1] += f_1.y + f_2.y + f_3.y;
        }
    }

    float acc = 0.f;
#pragma unroll
    for (int k = 0; k < 8; k++) acc += a[k] * b[k];

#pragma unroll
    for (int off = 16; off > 0; off >>= 1)
        acc += __shfl_down_sync(0xFFFFFFFFu, acc, off);

    if (lane == 0) out[w] = acc * (1.0f / 16.0f);   // (1/4)*(1/4)
}

extern "C" void kernel_launch(void* const* d_in, const int* in_sizes, int n_in,
                              void* d_out, int out_size) {
    const float* user_emb = (const float*)d_in[0];
    const float* item_emb = (const float*)d_in[1];
    const float* vals     = (const float*)d_in[2];
    const int*   rows     = (const int*)d_in[3];
    const int*   cols     = (const int*)d_in[4];
    const int*   users    = (const int*)d_in[5];
    const int*   items    = (const int*)d_in[6];
    float* out = (float*)d_out;

    __half *h0, *h1, *h2, *h3;
    int *counts, *rowptr, *fill;
    int2 *edges;
    cudaGetSymbolAddress((void**)&h0, g_h0);
    cudaGetSymbolAddress((void**)&h1, g_h1);
    cudaGetSymbolAddress((void**)&h2, g_h2);
    cudaGetSymbolAddress((void**)&h3, g_h3);
    cudaGetSymbolAddress((void**)&counts, g_counts);
    cudaGetSymbolAddress((void**)&rowptr, g_rowptr);
    cudaGetSymbolAddress((void**)&fill, g_fill);
    cudaGetSymbolAddress((void**)&edges, g_edges);

    // ---- CSR build ----
    zero_counts_kernel<<<(N_NODES + 255) / 256, 256>>>(counts);
    hist_kernel<<<(NNZ + 255) / 256, 256>>>(rows, counts);
    scan_kernel<<<1, SCAN_T>>>(counts, rowptr, fill);
    scatter_kernel<<<(NNZ + 255) / 256, 256>>>(rows, cols, vals, fill, edges);

    // ---- fp32 -> fp16 base embeddings ----
    to_half_kernel<<<(N_NODES * D4 + 255) / 256, 256>>>(user_emb, item_emb, h0);

    // ---- 3 SpMM passes (warp per row) ----
    const int spmm_blocks = (N_NODES * 32 + 255) / 256;
    spmm_csr_kernel<<<spmm_blocks, 256>>>(h0, rowptr, edges, h1);
    spmm_csr_kernel<<<spmm_blocks, 256>>>(h1, rowptr, edges, h2);
    spmm_csr_kernel<<<spmm_blocks, 256>>>(h2, rowptr, edges, h3);

    // ---- final gather + dot ----
    gather_dot_kernel<<<(BATCH * 32 + 255) / 256, 256>>>(
        user_emb, item_emb, users, items, h1, h2, h3, out);
}

// round 6
// speedup vs baseline: 5.9566x; 1.1535x over previous
#include <cuda_runtime.h>
#include <cuda_fp16.h>
#include <cstdint>

// ---------------- problem constants ----------------
#define USER_NUM 100000
#define ITEM_NUM 50000
#define N_NODES  150000      // USER_NUM + ITEM_NUM
#define REC_DIM  256
#define D4       64          // REC_DIM / 4 (float4 per row)
#define DH4      32          // REC_DIM / 8 (uint4-of-8-halves per row)
#define NNZ      6400000
#define BATCH    16384
#define SCAN_BLOCK 512
#define SCAN_NBLK  ((N_NODES + SCAN_BLOCK - 1) / SCAN_BLOCK)   // 293

// ---------------- static device scratch (no runtime allocation) ----------------
__device__ __half g_h0[(size_t)N_NODES * REC_DIM];   // 76.8 MB each
__device__ __half g_h1[(size_t)N_NODES * REC_DIM];
__device__ __half g_h2[(size_t)N_NODES * REC_DIM];
__device__ __half g_h3[(size_t)N_NODES * REC_DIM];
__device__ int    g_counts[N_NODES];
__device__ int    g_local[N_NODES];
__device__ int    g_blocksums[SCAN_BLOCK];           // >= SCAN_NBLK
__device__ int    g_rowptr[N_NODES + 1];
__device__ int    g_fill[N_NODES];
__device__ int2   g_edges[NNZ];                      // {col, val-as-int-bits}

// ---------------- fused: zero counts + fp32 concat -> fp16 ----------------
__global__ void zero_and_tohalf_kernel(const float* __restrict__ user_emb,
                                       const float* __restrict__ item_emb,
                                       __half* __restrict__ h0,
                                       int* __restrict__ counts) {
    int i = blockIdx.x * blockDim.x + threadIdx.x;   // < N_NODES * D4
    if (i < N_NODES) counts[i] = 0;
    if (i >= N_NODES * D4) return;
    const int user_f4 = USER_NUM * D4;
    float4 f = (i < user_f4) ? ((const float4*)user_emb)[i]
                             : ((const float4*)item_emb)[i - user_f4];
    __half2 lo = __floats2half2_rn(f.x, f.y);
    __half2 hi = __floats2half2_rn(f.z, f.w);
    uint2 o;
    o.x = *(unsigned int*)&lo;
    o.y = *(unsigned int*)&hi;
    ((uint2*)h0)[i] = o;
}

// ---------------- histogram: 4 edges per thread ----------------
__global__ void hist_kernel(const int4* __restrict__ rows4, int* __restrict__ counts) {
    int i = blockIdx.x * blockDim.x + threadIdx.x;
    if (i >= NNZ / 4) return;
    int4 r = __ldcs(&rows4[i]);
    atomicAdd(&counts[r.x], 1);
    atomicAdd(&counts[r.y], 1);
    atomicAdd(&counts[r.z], 1);
    atomicAdd(&counts[r.w], 1);
}

// ---------------- 3-kernel coalesced scan ----------------
__global__ void scan_local_kernel(const int* __restrict__ counts,
                                  int* __restrict__ local,
                                  int* __restrict__ blocksums) {
    __shared__ int s[SCAN_BLOCK];
    int gid = blockIdx.x * SCAN_BLOCK + threadIdx.x;
    int v = (gid < N_NODES) ? counts[gid] : 0;
    s[threadIdx.x] = v;
    __syncthreads();
    for (int off = 1; off < SCAN_BLOCK; off <<= 1) {
        int t = (threadIdx.x >= off) ? s[threadIdx.x - off] : 0;
        __syncthreads();
        s[threadIdx.x] += t;
        __syncthreads();
    }
    if (gid < N_NODES) local[gid] = s[threadIdx.x] - v;   // exclusive
    if (threadIdx.x == SCAN_BLOCK - 1) blocksums[blockIdx.x] = s[threadIdx.x];
}

__global__ void scan_blocks_kernel(int* __restrict__ blocksums) {
    __shared__ int s[SCAN_BLOCK];
    int t = threadIdx.x;
    int v = (t < SCAN_NBLK) ? blocksums[t] : 0;
    s[t] = v;
    __syncthreads();
    for (int off = 1; off < SCAN_BLOCK; off <<= 1) {
        int x = (t >= off) ? s[t - off] : 0;
        __syncthreads();
        s[t] += x;
        __syncthreads();
    }
    if (t < SCAN_NBLK) blocksums[t] = s[t] - v;           // exclusive
}

__global__ void scan_add_kernel(const int* __restrict__ local,
                                const int* __restrict__ blocksums,
                                int* __restrict__ row_ptr,
                                int* __restrict__ fill) {
    int gid = blockIdx.x * SCAN_BLOCK + threadIdx.x;
    if (gid < N_NODES) {
        int v = local[gid] + blocksums[blockIdx.x];
        row_ptr[gid] = v;
        fill[gid] = v;
    }
    if (gid == 0) row_ptr[N_NODES] = NNZ;
}

// ---------------- scatter: 4 edges per thread ----------------
__global__ void scatter_kernel(const int4* __restrict__ rows4,
                               const int4* __restrict__ cols4,
                               const float4* __restrict__ vals4,
                               int* __restrict__ fill,
                               int2* __restrict__ edges) {
    int i = blockIdx.x * blockDim.x + threadIdx.x;
    if (i >= NNZ / 4) return;
    int4 r = __ldcs(&rows4[i]);
    int4 c = __ldcs(&cols4[i]);
    float4 v = __ldcs(&vals4[i]);
    int p0 = atomicAdd(&fill[r.x], 1);
    int p1 = atomicAdd(&fill[r.y], 1);
    int p2 = atomicAdd(&fill[r.z], 1);
    int p3 = atomicAdd(&fill[r.w], 1);
    edges[p0] = make_int2(c.x, __float_as_int(v.x));
    edges[p1] = make_int2(c.y, __float_as_int(v.y));
    edges[p2] = make_int2(c.z, __float_as_int(v.z));
    edges[p3] = make_int2(c.w, __float_as_int(v.w));
}

// ---------------- CSR row-gather SpMM (fp16 storage, fp32 accumulate) --------
// One warp per output row. Lane owns 8 features (one uint4 of halves).
__device__ __forceinline__ void fma8(float* acc, uint4 h, float v) {
    const __half2* hp = (const __half2*)&h;
#pragma unroll
    for (int k = 0; k < 4; k++) {
        float2 f = __half22float2(hp[k]);
        acc[2 * k]     += v * f.x;
        acc[2 * k + 1] += v * f.y;
    }
}

__global__ void spmm_csr_kernel(const __half* __restrict__ cur,
                                const int* __restrict__ row_ptr,
                                const int2* __restrict__ edges,
                                __half* __restrict__ next) {
    int r = (blockIdx.x * blockDim.x + threadIdx.x) >> 5;
    if (r >= N_NODES) return;
    int lane = threadIdx.x & 31;

    int start = __ldg(&row_ptr[r]);
    int end   = __ldg(&row_ptr[r + 1]);

    float acc[8];
#pragma unroll
    for (int k = 0; k < 8; k++) acc[k] = 0.f;

    const uint4* curv = (const uint4*)cur;   // 8 halves each

    int e = start;
    for (; e + 4 <= end; e += 4) {
        int2 e0 = __ldcs(&edges[e + 0]);
        int2 e1 = __ldcs(&edges[e + 1]);
        int2 e2 = __ldcs(&edges[e + 2]);
        int2 e3 = __ldcs(&edges[e + 3]);
        uint4 h0 = __ldg(&curv[(size_t)e0.x * DH4 + lane]);
        uint4 h1 = __ldg(&curv[(size_t)e1.x * DH4 + lane]);
        uint4 h2 = __ldg(&curv[(size_t)e2.x * DH4 + lane]);
        uint4 h3 = __ldg(&curv[(size_t)e3.x * DH4 + lane]);
        fma8(acc, h0, __int_as_float(e0.y));
        fma8(acc, h1, __int_as_float(e1.y));
        fma8(acc, h2, __int_as_float(e2.y));
        fma8(acc, h3, __int_as_float(e3.y));
    }
    for (; e < end; e++) {
        int2 ed = __ldcs(&edges[e]);
        uint4 h = __ldg(&curv[(size_t)ed.x * DH4 + lane]);
        fma8(acc, h, __int_as_float(ed.y));
    }

    uint4 o;
    __half2* op = (__half2*)&o;
#pragma unroll
    for (int k = 0; k < 4; k++)
        op[k] = __floats2half2_rn(acc[2 * k], acc[2 * k + 1]);
    __stcs(&((uint4*)next)[(size_t)r * DH4 + lane], o);    // streaming store
}

// ---------------- final gather + dot ----------------
__global__ void gather_dot_kernel(const float* __restrict__ user_emb,
                                  const float* __restrict__ item_emb,
                                  const int*   __restrict__ users,
                                  const int*   __restrict__ items,
                                  const __half* __restrict__ h1,
                                  const __half* __restrict__ h2,
                                  const __half* __restrict__ h3,
                                  float*       __restrict__ out) {
    int w = (blockIdx.x * blockDim.x + threadIdx.x) >> 5;
    if (w >= BATCH) return;
    int lane = threadIdx.x & 31;

    int u  = users[w];
    int it = items[w];
    size_t un  = (size_t)u;
    size_t in_ = (size_t)(USER_NUM + it);

    const uint4* h1v = (const uint4*)h1;
    const uint4* h2v = (const uint4*)h2;
    const uint4* h3v = (const uint4*)h3;

    float a[8], b[8];
    {
        const float4* p = (const float4*)user_emb + (size_t)u * D4;
        float4 f0 = p[lane * 2], f1 = p[lane * 2 + 1];
        a[0] = f0.x; a[1] = f0.y; a[2] = f0.z; a[3] = f0.w;
        a[4] = f1.x; a[5] = f1.y; a[6] = f1.z; a[7] = f1.w;
        uint4 q1 = h1v[un * DH4 + lane];
        uint4 q2 = h2v[un * DH4 + lane];
        uint4 q3 = h3v[un * DH4 + lane];
        const __half2 *p1 = (const __half2*)&q1, *p2 = (const __half2*)&q2, *p3 = (const __half2*)&q3;
#pragma unroll
        for (int k = 0; k < 4; k++) {
            float2 f_1 = __half22float2(p1[k]);
            float2 f_2 = __half22float2(p2[k]);
            float2 f_3 = __half22float2(p3[k]);
            a[2*k]   += f_1.x + f_2.x + f_3.x;
            a[2*k+1] += f_1.y + f_2.y + f_3.y;
        }
    }
    {
        const float4* p = (const float4*)item_emb + (size_t)it * D4;
        float4 f0 = p[lane * 2], f1 = p[lane * 2 + 1];
        b[0] = f0.x; b[1] = f0.y; b[2] = f0.z; b[3] = f0.w;
        b[4] = f1.x; b[5] = f1.y; b[6] = f1.z; b[7] = f1.w;
        uint4 q1 = h1v[in_ * DH4 + lane];
        uint4 q2 = h2v[in_ * DH4 + lane];
        uint4 q3 = h3v[in_ * DH4 + lane];
        const __half2 *p1 = (const __half2*)&q1, *p2 = (const __half2*)&q2, *p3 = (const __half2*)&q3;
#pragma unroll
        for (int k = 0; k < 4; k++) {
            float2 f_1 = __half22float2(p1[k]);
            float2 f_2 = __half22float2(p2[k]);
            float2 f_3 = __half22float2(p3[k]);
            b[2*k]   += f_1.x + f_2.x + f_3.x;
            b[2*k+1] += f_1.y + f_2.y + f_3.y;
        }
    }

    float acc = 0.f;
#pragma unroll
    for (int k = 0; k < 8; k++) acc += a[k] * b[k];

#pragma unroll
    for (int off = 16; off > 0; off >>= 1)
        acc += __shfl_down_sync(0xFFFFFFFFu, acc, off);

    if (lane == 0) out[w] = acc * (1.0f / 16.0f);   // (1/4)*(1/4)
}

extern "C" void kernel_launch(void* const* d_in, const int* in_sizes, int n_in,
                              void* d_out, int out_size) {
    const float* user_emb = (const float*)d_in[0];
    const float* item_emb = (const float*)d_in[1];
    const float* vals     = (const float*)d_in[2];
    const int*   rows     = (const int*)d_in[3];
    const int*   cols     = (const int*)d_in[4];
    const int*   users    = (const int*)d_in[5];
    const int*   items    = (const int*)d_in[6];
    float* out = (float*)d_out;

    __half *h0, *h1, *h2, *h3;
    int *counts, *local, *blocksums, *rowptr, *fill;
    int2 *edges;
    cudaGetSymbolAddress((void**)&h0, g_h0);
    cudaGetSymbolAddress((void**)&h1, g_h1);
    cudaGetSymbolAddress((void**)&h2, g_h2);
    cudaGetSymbolAddress((void**)&h3, g_h3);
    cudaGetSymbolAddress((void**)&counts, g_counts);
    cudaGetSymbolAddress((void**)&local, g_local);
    cudaGetSymbolAddress((void**)&blocksums, g_blocksums);
    cudaGetSymbolAddress((void**)&rowptr, g_rowptr);
    cudaGetSymbolAddress((void**)&fill, g_fill);
    cudaGetSymbolAddress((void**)&edges, g_edges);

    // ---- fused zero + fp16 convert ----
    zero_and_tohalf_kernel<<<(N_NODES * D4 + 255) / 256, 256>>>(
        user_emb, item_emb, h0, counts);

    // ---- histogram (4 edges/thread) ----
    hist_kernel<<<(NNZ / 4 + 255) / 256, 256>>>((const int4*)rows, counts);

    // ---- 3-kernel coalesced scan ----
    scan_local_kernel<<<SCAN_NBLK, SCAN_BLOCK>>>(counts, local, blocksums);
    scan_blocks_kernel<<<1, SCAN_BLOCK>>>(blocksums);
    scan_add_kernel<<<SCAN_NBLK, SCAN_BLOCK>>>(local, blocksums, rowptr, fill);

    // ---- scatter (4 edges/thread) ----
    scatter_kernel<<<(NNZ / 4 + 255) / 256, 256>>>(
        (const int4*)rows, (const int4*)cols, (const float4*)vals, fill, edges);

    // ---- 3 SpMM passes (warp per row) ----
    const int spmm_blocks = (N_NODES * 32 + 255) / 256;
    spmm_csr_kernel<<<spmm_blocks, 256>>>(h0, rowptr, edges, h1);
    spmm_csr_kernel<<<spmm_blocks, 256>>>(h1, rowptr, edges, h2);
    spmm_csr_kernel<<<spmm_blocks, 256>>>(h2, rowptr, edges, h3);

    // ---- final gather + dot ----
    gather_dot_kernel<<<(BATCH * 32 + 255) / 256, 256>>>(
        user_emb, item_emb, users, items, h1, h2, h3, out);
}

// round 10
// speedup vs baseline: 7.3746x; 1.2380x over previous
#include <cuda_runtime.h>
#include <cuda_fp16.h>
#include <cstdint>

// ---------------- problem constants ----------------
#define USER_NUM 100000
#define ITEM_NUM 50000
#define N_NODES  150000      // USER_NUM + ITEM_NUM
#define REC_DIM  256
#define D4       64          // REC_DIM / 4 (float4 per row)
#define DH4      32          // REC_DIM / 8 (uint4-of-8-halves per row)
#define NNZ      6400000
#define BATCH    16384
#define SCAN_BLOCK 512
#define SCAN_NBLK  ((N_NODES + SCAN_BLOCK - 1) / SCAN_BLOCK)   // 293

// ---------------- static device scratch (no runtime allocation) ----------------
__device__ __half g_h0[(size_t)N_NODES * REC_DIM];   // 76.8 MB each
__device__ __half g_h1[(size_t)N_NODES * REC_DIM];
__device__ __half g_h2[(size_t)N_NODES * REC_DIM];
__device__ __half g_h3c[(size_t)2 * BATCH * REC_DIM]; // compact pass-3 output (16.8 MB)
__device__ int    g_counts[N_NODES];
__device__ int    g_local[N_NODES];
__device__ int    g_blocksums[SCAN_NBLK];
__device__ int    g_rowptr[N_NODES + 1];
__device__ int    g_fill[N_NODES];
__device__ int2   g_edges[NNZ];                      // {col, val-as-int-bits}

// ---------------- fused: zero counts + fp32 concat -> fp16 ----------------
__global__ void zero_and_tohalf_kernel(const float* __restrict__ user_emb,
                                       const float* __restrict__ item_emb,
                                       __half* __restrict__ h0,
                                       int* __restrict__ counts) {
    int i = blockIdx.x * blockDim.x + threadIdx.x;   // < N_NODES * D4
    if (i < N_NODES) counts[i] = 0;
    if (i >= N_NODES * D4) return;
    const int user_f4 = USER_NUM * D4;
    float4 f = (i < user_f4) ? ((const float4*)user_emb)[i]
                             : ((const float4*)item_emb)[i - user_f4];
    __half2 lo = __floats2half2_rn(f.x, f.y);
    __half2 hi = __floats2half2_rn(f.z, f.w);
    uint2 o;
    o.x = *(unsigned int*)&lo;
    o.y = *(unsigned int*)&hi;
    ((uint2*)h0)[i] = o;
}

// ---------------- histogram: 4 edges per thread ----------------
__global__ void hist_kernel(const int4* __restrict__ rows4, int* __restrict__ counts) {
    int i = blockIdx.x * blockDim.x + threadIdx.x;
    if (i >= NNZ / 4) return;
    int4 r = __ldcs(&rows4[i]);
    atomicAdd(&counts[r.x], 1);
    atomicAdd(&counts[r.y], 1);
    atomicAdd(&counts[r.z], 1);
    atomicAdd(&counts[r.w], 1);
}

// ---------------- 2-kernel coalesced scan ----------------
__global__ void scan_local_kernel(const int* __restrict__ counts,
                                  int* __restrict__ local,
                                  int* __restrict__ blocksums) {
    __shared__ int s[SCAN_BLOCK];
    int gid = blockIdx.x * SCAN_BLOCK + threadIdx.x;
    int v = (gid < N_NODES) ? counts[gid] : 0;
    s[threadIdx.x] = v;
    __syncthreads();
    for (int off = 1; off < SCAN_BLOCK; off <<= 1) {
        int t = (threadIdx.x >= off) ? s[threadIdx.x - off] : 0;
        __syncthreads();
        s[threadIdx.x] += t;
        __syncthreads();
    }
    if (gid < N_NODES) local[gid] = s[threadIdx.x] - v;   // exclusive
    if (threadIdx.x == SCAN_BLOCK - 1) blocksums[blockIdx.x] = s[threadIdx.x];
}

// scan_add: each block redundantly scans the 293 block sums in smem (cheap),
// picks its own exclusive prefix, writes row_ptr + fill.
__global__ void scan_add_kernel(const int* __restrict__ local,
                                const int* __restrict__ blocksums,
                                int* __restrict__ row_ptr,
                                int* __restrict__ fill) {
    __shared__ int s[SCAN_BLOCK];
    int t = threadIdx.x;
    s[t] = (t < SCAN_NBLK) ? blocksums[t] : 0;
    __syncthreads();
    for (int off = 1; off < SCAN_BLOCK; off <<= 1) {
        int x = (t >= off) ? s[t - off] : 0;
        __syncthreads();
        s[t] += x;
        __syncthreads();
    }
    // exclusive prefix for this block = inclusive[blockIdx.x - 1]
    int blkoff = (blockIdx.x == 0) ? 0 : s[blockIdx.x - 1];
    int gid = blockIdx.x * SCAN_BLOCK + t;
    if (gid < N_NODES) {
        int v = local[gid] + blkoff;
        row_ptr[gid] = v;
        fill[gid] = v;
    }
    if (gid == 0) row_ptr[N_NODES] = NNZ;
}

// ---------------- scatter: 4 edges per thread ----------------
__global__ void scatter_kernel(const int4* __restrict__ rows4,
                               const int4* __restrict__ cols4,
                               const float4* __restrict__ vals4,
                               int* __restrict__ fill,
                               int2* __restrict__ edges) {
    int i = blockIdx.x * blockDim.x + threadIdx.x;
    if (i >= NNZ / 4) return;
    int4 r = __ldcs(&rows4[i]);
    int4 c = __ldcs(&cols4[i]);
    float4 v = __ldcs(&vals4[i]);
    int p0 = atomicAdd(&fill[r.x], 1);
    int p1 = atomicAdd(&fill[r.y], 1);
    int p2 = atomicAdd(&fill[r.z], 1);
    int p3 = atomicAdd(&fill[r.w], 1);
    edges[p0] = make_int2(c.x, __float_as_int(v.x));
    edges[p1] = make_int2(c.y, __float_as_int(v.y));
    edges[p2] = make_int2(c.z, __float_as_int(v.z));
    edges[p3] = make_int2(c.w, __float_as_int(v.w));
}

// ---------------- CSR row-gather core (fp16 storage, fp32 accumulate) --------
__device__ __forceinline__ void fma8(float* acc, uint4 h, float v) {
    const __half2* hp = (const __half2*)&h;
#pragma unroll
    for (int k = 0; k < 4; k++) {
        float2 f = __half22float2(hp[k]);
        acc[2 * k]     += v * f.x;
        acc[2 * k + 1] += v * f.y;
    }
}

__device__ __forceinline__ void spmm_row(const uint4* __restrict__ curv,
                                         const int2* __restrict__ edges,
                                         int start, int end, int lane,
                                         float* acc) {
#pragma unroll
    for (int k = 0; k < 8; k++) acc[k] = 0.f;
    int e = start;
    for (; e + 4 <= end; e += 4) {
        int2 e0 = __ldcs(&edges[e + 0]);
        int2 e1 = __ldcs(&edges[e + 1]);
        int2 e2 = __ldcs(&edges[e + 2]);
        int2 e3 = __ldcs(&edges[e + 3]);
        uint4 h0 = __ldg(&curv[(size_t)e0.x * DH4 + lane]);
        uint4 h1 = __ldg(&curv[(size_t)e1.x * DH4 + lane]);
        uint4 h2 = __ldg(&curv[(size_t)e2.x * DH4 + lane]);
        uint4 h3 = __ldg(&curv[(size_t)e3.x * DH4 + lane]);
        fma8(acc, h0, __int_as_float(e0.y));
        fma8(acc, h1, __int_as_float(e1.y));
        fma8(acc, h2, __int_as_float(e2.y));
        fma8(acc, h3, __int_as_float(e3.y));
    }
    for (; e < end; e++) {
        int2 ed = __ldcs(&edges[e]);
        uint4 h = __ldg(&curv[(size_t)ed.x * DH4 + lane]);
        fma8(acc, h, __int_as_float(ed.y));
    }
}

__device__ __forceinline__ uint4 pack8(const float* acc) {
    uint4 o;
    __half2* op = (__half2*)&o;
#pragma unroll
    for (int k = 0; k < 4; k++)
        op[k] = __floats2half2_rn(acc[2 * k], acc[2 * k + 1]);
    return o;
}

// Full SpMM: one warp per output row (all N_NODES rows).
__global__ void spmm_csr_kernel(const __half* __restrict__ cur,
                                const int* __restrict__ row_ptr,
                                const int2* __restrict__ edges,
                                __half* __restrict__ next) {
    int r = (blockIdx.x * blockDim.x + threadIdx.x) >> 5;
    if (r >= N_NODES) return;
    int lane = threadIdx.x & 31;
    int start = __ldg(&row_ptr[r]);
    int end   = __ldg(&row_ptr[r + 1]);
    float acc[8];
    spmm_row((const uint4*)cur, edges, start, end, lane, acc);
    __stcs(&((uint4*)next)[(size_t)r * DH4 + lane], pack8(acc));
}

// Restricted pass-3 SpMM: only the 2*BATCH batch rows, compact output.
// Slot w < BATCH -> row users[w]; slot w >= BATCH -> row USER_NUM+items[w-BATCH].
// Duplicate rows recompute identical values (benign, deterministic).
__global__ void spmm_batch_kernel(const __half* __restrict__ cur,
                                  const int* __restrict__ row_ptr,
                                  const int2* __restrict__ edges,
                                  const int* __restrict__ users,
                                  const int* __restrict__ items,
                                  __half* __restrict__ h3c) {
    int w = (blockIdx.x * blockDim.x + threadIdx.x) >> 5;
    if (w >= 2 * BATCH) return;
    int lane = threadIdx.x & 31;
    int r = (w < BATCH) ? __ldg(&users[w]) : USER_NUM + __ldg(&items[w - BATCH]);
    int start = __ldg(&row_ptr[r]);
    int end   = __ldg(&row_ptr[r + 1]);
    float acc[8];
    spmm_row((const uint4*)cur, edges, start, end, lane, acc);
    __stcs(&((uint4*)h3c)[(size_t)w * DH4 + lane], pack8(acc));
}

// ---------------- final gather + dot ----------------
// One warp per batch element; lane owns 8 features. h3 read from compact buffer.
__global__ void gather_dot_kernel(const float* __restrict__ user_emb,
                                  const float* __restrict__ item_emb,
                                  const int*   __restrict__ users,
                                  const int*   __restrict__ items,
                                  const __half* __restrict__ h1,
                                  const __half* __restrict__ h2,
                                  const __half* __restrict__ h3c,
                                  float*       __restrict__ out) {
    int w = (blockIdx.x * blockDim.x + threadIdx.x) >> 5;
    if (w >= BATCH) return;
    int lane = threadIdx.x & 31;

    int u  = users[w];
    int it = items[w];
    size_t un  = (size_t)u;
    size_t in_ = (size_t)(USER_NUM + it);

    const uint4* h1v = (const uint4*)h1;
    const uint4* h2v = (const uint4*)h2;
    const uint4* h3v = (const uint4*)h3c;

    float a[8], b[8];
    {
        const float4* p = (const float4*)user_emb + (size_t)u * D4;
        float4 f0 = p[lane * 2], f1 = p[lane * 2 + 1];
        a[0] = f0.x; a[1] = f0.y; a[2] = f0.z; a[3] = f0.w;
        a[4] = f1.x; a[5] = f1.y; a[6] = f1.z; a[7] = f1.w;
        uint4 q1 = h1v[un * DH4 + lane];
        uint4 q2 = h2v[un * DH4 + lane];
        uint4 q3 = h3v[(size_t)w * DH4 + lane];
        const __half2 *p1 = (const __half2*)&q1, *p2 = (const __half2*)&q2, *p3 = (const __half2*)&q3;
#pragma unroll
        for (int k = 0; k < 4; k++) {
            float2 f_1 = __half22float2(p1[k]);
            float2 f_2 = __half22float2(p2[k]);
            float2 f_3 = __half22float2(p3[k]);
            a[2*k]   += f_1.x + f_2.x + f_3.x;
            a[2*k+1] += f_1.y + f_2.y + f_3.y;
        }
    }
    {
        const float4* p = (const float4*)item_emb + (size_t)it * D4;
        float4 f0 = p[lane * 2], f1 = p[lane * 2 + 1];
        b[0] = f0.x; b[1] = f0.y; b[2] = f0.z; b[3] = f0.w;
        b[4] = f1.x; b[5] = f1.y; b[6] = f1.z; b[7] = f1.w;
        uint4 q1 = h1v[in_ * DH4 + lane];
        uint4 q2 = h2v[in_ * DH4 + lane];
        uint4 q3 = h3v[(size_t)(w + BATCH) * DH4 + lane];
        const __half2 *p1 = (const __half2*)&q1, *p2 = (const __half2*)&q2, *p3 = (const __half2*)&q3;
#pragma unroll
        for (int k = 0; k < 4; k++) {
            float2 f_1 = __half22float2(p1[k]);
            float2 f_2 = __half22float2(p2[k]);
            float2 f_3 = __half22float2(p3[k]);
            b[2*k]   += f_1.x + f_2.x + f_3.x;
            b[2*k+1] += f_1.y + f_2.y + f_3.y;
        }
    }

    float acc = 0.f;
#pragma unroll
    for (int k = 0; k < 8; k++) acc += a[k] * b[k];

#pragma unroll
    for (int off = 16; off > 0; off >>= 1)
        acc += __shfl_down_sync(0xFFFFFFFFu, acc, off);

    if (lane == 0) out[w] = acc * (1.0f / 16.0f);   // (1/4)*(1/4)
}

extern "C" void kernel_launch(void* const* d_in, const int* in_sizes, int n_in,
                              void* d_out, int out_size) {
    const float* user_emb = (const float*)d_in[0];
    const float* item_emb = (const float*)d_in[1];
    const float* vals     = (const float*)d_in[2];
    const int*   rows     = (const int*)d_in[3];
    const int*   cols     = (const int*)d_in[4];
    const int*   users    = (const int*)d_in[5];
    const int*   items    = (const int*)d_in[6];
    float* out = (float*)d_out;

    __half *h0, *h1, *h2, *h3c;
    int *counts, *local, *blocksums, *rowptr, *fill;
    int2 *edges;
    cudaGetSymbolAddress((void**)&h0, g_h0);
    cudaGetSymbolAddress((void**)&h1, g_h1);
    cudaGetSymbolAddress((void**)&h2, g_h2);
    cudaGetSymbolAddress((void**)&h3c, g_h3c);
    cudaGetSymbolAddress((void**)&counts, g_counts);
    cudaGetSymbolAddress((void**)&local, g_local);
    cudaGetSymbolAddress((void**)&blocksums, g_blocksums);
    cudaGetSymbolAddress((void**)&rowptr, g_rowptr);
    cudaGetSymbolAddress((void**)&fill, g_fill);
    cudaGetSymbolAddress((void**)&edges, g_edges);

    // ---- fused zero + fp16 convert ----
    zero_and_tohalf_kernel<<<(N_NODES * D4 + 255) / 256, 256>>>(
        user_emb, item_emb, h0, counts);

    // ---- histogram (4 edges/thread) ----
    hist_kernel<<<(NNZ / 4 + 255) / 256, 256>>>((const int4*)rows, counts);

    // ---- 2-kernel coalesced scan ----
    scan_local_kernel<<<SCAN_NBLK, SCAN_BLOCK>>>(counts, local, blocksums);
    scan_add_kernel<<<SCAN_NBLK, SCAN_BLOCK>>>(local, blocksums, rowptr, fill);

    // ---- scatter (4 edges/thread) ----
    scatter_kernel<<<(NNZ / 4 + 255) / 256, 256>>>(
        (const int4*)rows, (const int4*)cols, (const float4*)vals, fill, edges);

    // ---- 2 full SpMM passes + restricted pass 3 ----
    const int spmm_blocks = (N_NODES * 32 + 255) / 256;
    spmm_csr_kernel<<<spmm_blocks, 256>>>(h0, rowptr, edges, h1);
    spmm_csr_kernel<<<spmm_blocks, 256>>>(h1, rowptr, edges, h2);
    spmm_batch_kernel<<<(2 * BATCH * 32 + 255) / 256, 256>>>(
        h2, rowptr, edges, users, items, h3c);

    // ---- final gather + dot ----
    gather_dot_kernel<<<(BATCH * 32 + 255) / 256, 256>>>(
        user_emb, item_emb, users, items, h1, h2, h3c, out);
}

// round 11
// speedup vs baseline: 7.4691x; 1.0128x over previous
#include <cuda_runtime.h>
#include <cuda_fp16.h>
#include <cstdint>

// ---------------- problem constants ----------------
#define USER_NUM 100000
#define ITEM_NUM 50000
#define N_NODES  150000      // USER_NUM + ITEM_NUM
#define REC_DIM  256
#define D4       64          // REC_DIM / 4 (float4 per row)
#define DH4      32          // REC_DIM / 8 (uint4-of-8-halves per row)
#define NNZ      6400000
#define BATCH    16384
#define SCAN_BLOCK 512
#define SCAN_NBLK  ((N_NODES + SCAN_BLOCK - 1) / SCAN_BLOCK)   // 293

// ---------------- static device scratch (no runtime allocation) ----------------
__device__ __half g_h0[(size_t)N_NODES * REC_DIM];   // 76.8 MB each
__device__ __half g_h1[(size_t)N_NODES * REC_DIM];
__device__ __half g_h2[(size_t)N_NODES * REC_DIM];
__device__ __half g_h3c[(size_t)2 * BATCH * REC_DIM]; // compact pass-3 output (16.8 MB)
__device__ int    g_counts[N_NODES];
__device__ int    g_local[N_NODES];
__device__ int    g_blocksums[SCAN_NBLK];
__device__ int    g_rowptr[N_NODES + 1];
__device__ int    g_fill[N_NODES];
__device__ int2   g_edges[NNZ];                      // {col, val-as-int-bits}

// ---------------- fused: zero counts + fp32 concat -> fp16 ----------------
__global__ void zero_and_tohalf_kernel(const float* __restrict__ user_emb,
                                       const float* __restrict__ item_emb,
                                       __half* __restrict__ h0,
                                       int* __restrict__ counts) {
    int i = blockIdx.x * blockDim.x + threadIdx.x;   // < N_NODES * D4
    if (i < N_NODES) counts[i] = 0;
    if (i >= N_NODES * D4) return;
    const int user_f4 = USER_NUM * D4;
    float4 f = (i < user_f4) ? ((const float4*)user_emb)[i]
                             : ((const float4*)item_emb)[i - user_f4];
    __half2 lo = __floats2half2_rn(f.x, f.y);
    __half2 hi = __floats2half2_rn(f.z, f.w);
    uint2 o;
    o.x = *(unsigned int*)&lo;
    o.y = *(unsigned int*)&hi;
    ((uint2*)h0)[i] = o;
}

// ---------------- histogram: 8 edges per thread ----------------
__global__ void hist_kernel(const int4* __restrict__ rows4, int* __restrict__ counts) {
    int i = blockIdx.x * blockDim.x + threadIdx.x;
    if (i >= NNZ / 8) return;
    int4 r0 = __ldcs(&rows4[2 * i]);
    int4 r1 = __ldcs(&rows4[2 * i + 1]);
    atomicAdd(&counts[r0.x], 1);
    atomicAdd(&counts[r0.y], 1);
    atomicAdd(&counts[r0.z], 1);
    atomicAdd(&counts[r0.w], 1);
    atomicAdd(&counts[r1.x], 1);
    atomicAdd(&counts[r1.y], 1);
    atomicAdd(&counts[r1.z], 1);
    atomicAdd(&counts[r1.w], 1);
}

// ---------------- 2-kernel coalesced scan ----------------
__global__ void scan_local_kernel(const int* __restrict__ counts,
                                  int* __restrict__ local,
                                  int* __restrict__ blocksums) {
    __shared__ int s[SCAN_BLOCK];
    int gid = blockIdx.x * SCAN_BLOCK + threadIdx.x;
    int v = (gid < N_NODES) ? counts[gid] : 0;
    s[threadIdx.x] = v;
    __syncthreads();
    for (int off = 1; off < SCAN_BLOCK; off <<= 1) {
        int t = (threadIdx.x >= off) ? s[threadIdx.x - off] : 0;
        __syncthreads();
        s[threadIdx.x] += t;
        __syncthreads();
    }
    if (gid < N_NODES) local[gid] = s[threadIdx.x] - v;   // exclusive
    if (threadIdx.x == SCAN_BLOCK - 1) blocksums[blockIdx.x] = s[threadIdx.x];
}

// scan_add: each block redundantly scans the 293 block sums in smem (cheap),
// picks its own exclusive prefix, writes row_ptr + fill.
__global__ void scan_add_kernel(const int* __restrict__ local,
                                const int* __restrict__ blocksums,
                                int* __restrict__ row_ptr,
                                int* __restrict__ fill) {
    __shared__ int s[SCAN_BLOCK];
    int t = threadIdx.x;
    s[t] = (t < SCAN_NBLK) ? blocksums[t] : 0;
    __syncthreads();
    for (int off = 1; off < SCAN_BLOCK; off <<= 1) {
        int x = (t >= off) ? s[t - off] : 0;
        __syncthreads();
        s[t] += x;
        __syncthreads();
    }
    // exclusive prefix for this block = inclusive[blockIdx.x - 1]
    int blkoff = (blockIdx.x == 0) ? 0 : s[blockIdx.x - 1];
    int gid = blockIdx.x * SCAN_BLOCK + t;
    if (gid < N_NODES) {
        int v = local[gid] + blkoff;
        row_ptr[gid] = v;
        fill[gid] = v;
    }
    if (gid == 0) row_ptr[N_NODES] = NNZ;
}

// ---------------- scatter: 8 edges per thread ----------------
__global__ void scatter_kernel(const int4* __restrict__ rows4,
                               const int4* __restrict__ cols4,
                               const float4* __restrict__ vals4,
                               int* __restrict__ fill,
                               int2* __restrict__ edges) {
    int i = blockIdx.x * blockDim.x + threadIdx.x;
    if (i >= NNZ / 8) return;
    int4 ra = __ldcs(&rows4[2 * i]);
    int4 rb = __ldcs(&rows4[2 * i + 1]);
    int4 ca = __ldcs(&cols4[2 * i]);
    int4 cb = __ldcs(&cols4[2 * i + 1]);
    float4 va = __ldcs(&vals4[2 * i]);
    float4 vb = __ldcs(&vals4[2 * i + 1]);
    int p0 = atomicAdd(&fill[ra.x], 1);
    int p1 = atomicAdd(&fill[ra.y], 1);
    int p2 = atomicAdd(&fill[ra.z], 1);
    int p3 = atomicAdd(&fill[ra.w], 1);
    int p4 = atomicAdd(&fill[rb.x], 1);
    int p5 = atomicAdd(&fill[rb.y], 1);
    int p6 = atomicAdd(&fill[rb.z], 1);
    int p7 = atomicAdd(&fill[rb.w], 1);
    edges[p0] = make_int2(ca.x, __float_as_int(va.x));
    edges[p1] = make_int2(ca.y, __float_as_int(va.y));
    edges[p2] = make_int2(ca.z, __float_as_int(va.z));
    edges[p3] = make_int2(ca.w, __float_as_int(va.w));
    edges[p4] = make_int2(cb.x, __float_as_int(vb.x));
    edges[p5] = make_int2(cb.y, __float_as_int(vb.y));
    edges[p6] = make_int2(cb.z, __float_as_int(vb.z));
    edges[p7] = make_int2(cb.w, __float_as_int(vb.w));
}

// ---------------- CSR row-gather core (fp16 storage, fp32 accumulate) --------
__device__ __forceinline__ void fma8(float* acc, uint4 h, float v) {
    const __half2* hp = (const __half2*)&h;
#pragma unroll
    for (int k = 0; k < 4; k++) {
        float2 f = __half22float2(hp[k]);
        acc[2 * k]     += v * f.x;
        acc[2 * k + 1] += v * f.y;
    }
}

__device__ __forceinline__ void spmm_row(const uint4* __restrict__ curv,
                                         const int2* __restrict__ edges,
                                         int start, int end, int lane,
                                         float* acc) {
#pragma unroll
    for (int k = 0; k < 8; k++) acc[k] = 0.f;
    int e = start;
    for (; e + 4 <= end; e += 4) {
        int2 e0 = __ldcs(&edges[e + 0]);
        int2 e1 = __ldcs(&edges[e + 1]);
        int2 e2 = __ldcs(&edges[e + 2]);
        int2 e3 = __ldcs(&edges[e + 3]);
        uint4 h0 = __ldg(&curv[(size_t)e0.x * DH4 + lane]);
        uint4 h1 = __ldg(&curv[(size_t)e1.x * DH4 + lane]);
        uint4 h2 = __ldg(&curv[(size_t)e2.x * DH4 + lane]);
        uint4 h3 = __ldg(&curv[(size_t)e3.x * DH4 + lane]);
        fma8(acc, h0, __int_as_float(e0.y));
        fma8(acc, h1, __int_as_float(e1.y));
        fma8(acc, h2, __int_as_float(e2.y));
        fma8(acc, h3, __int_as_float(e3.y));
    }
    for (; e < end; e++) {
        int2 ed = __ldcs(&edges[e]);
        uint4 h = __ldg(&curv[(size_t)ed.x * DH4 + lane]);
        fma8(acc, h, __int_as_float(ed.y));
    }
}

__device__ __forceinline__ uint4 pack8(const float* acc) {
    uint4 o;
    __half2* op = (__half2*)&o;
#pragma unroll
    for (int k = 0; k < 4; k++)
        op[k] = __floats2half2_rn(acc[2 * k], acc[2 * k + 1]);
    return o;
}

// Full SpMM: one warp per output row (all N_NODES rows).
__global__ void spmm_csr_kernel(const __half* __restrict__ cur,
                                const int* __restrict__ row_ptr,
                                const int2* __restrict__ edges,
                                __half* __restrict__ next) {
    int r = (blockIdx.x * blockDim.x + threadIdx.x) >> 5;
    if (r >= N_NODES) return;
    int lane = threadIdx.x & 31;
    int start = __ldg(&row_ptr[r]);
    int end   = __ldg(&row_ptr[r + 1]);
    float acc[8];
    spmm_row((const uint4*)cur, edges, start, end, lane, acc);
    __stcs(&((uint4*)next)[(size_t)r * DH4 + lane], pack8(acc));
}

// Restricted pass-3 SpMM: only the 2*BATCH batch rows, compact output.
// Slot w < BATCH -> row users[w]; slot w >= BATCH -> row USER_NUM+items[w-BATCH].
// Duplicate rows recompute identical values (benign, deterministic).
__global__ void spmm_batch_kernel(const __half* __restrict__ cur,
                                  const int* __restrict__ row_ptr,
                                  const int2* __restrict__ edges,
                                  const int* __restrict__ users,
                                  const int* __restrict__ items,
                                  __half* __restrict__ h3c) {
    int w = (blockIdx.x * blockDim.x + threadIdx.x) >> 5;
    if (w >= 2 * BATCH) return;
    int lane = threadIdx.x & 31;
    int r = (w < BATCH) ? __ldg(&users[w]) : USER_NUM + __ldg(&items[w - BATCH]);
    int start = __ldg(&row_ptr[r]);
    int end   = __ldg(&row_ptr[r + 1]);
    float acc[8];
    spmm_row((const uint4*)cur, edges, start, end, lane, acc);
    __stcs(&((uint4*)h3c)[(size_t)w * DH4 + lane], pack8(acc));
}

// ---------------- final gather + dot ----------------
// One warp per batch element; lane owns 8 features. h3 read from compact buffer.
__global__ void gather_dot_kernel(const float* __restrict__ user_emb,
                                  const float* __restrict__ item_emb,
                                  const int*   __restrict__ users,
                                  const int*   __restrict__ items,
                                  const __half* __restrict__ h1,
                                  const __half* __restrict__ h2,
                                  const __half* __restrict__ h3c,
                                  float*       __restrict__ out) {
    int w = (blockIdx.x * blockDim.x + threadIdx.x) >> 5;
    if (w >= BATCH) return;
    int lane = threadIdx.x & 31;

    int u  = users[w];
    int it = items[w];
    size_t un  = (size_t)u;
    size_t in_ = (size_t)(USER_NUM + it);

    const uint4* h1v = (const uint4*)h1;
    const uint4* h2v = (const uint4*)h2;
    const uint4* h3v = (const uint4*)h3c;

    float a[8], b[8];
    {
        const float4* p = (const float4*)user_emb + (size_t)u * D4;
        float4 f0 = p[lane * 2], f1 = p[lane * 2 + 1];
        a[0] = f0.x; a[1] = f0.y; a[2] = f0.z; a[3] = f0.w;
        a[4] = f1.x; a[5] = f1.y; a[6] = f1.z; a[7] = f1.w;
        uint4 q1 = h1v[un * DH4 + lane];
        uint4 q2 = h2v[un * DH4 + lane];
        uint4 q3 = h3v[(size_t)w * DH4 + lane];
        const __half2 *p1 = (const __half2*)&q1, *p2 = (const __half2*)&q2, *p3 = (const __half2*)&q3;
#pragma unroll
        for (int k = 0; k < 4; k++) {
            float2 f_1 = __half22float2(p1[k]);
            float2 f_2 = __half22float2(p2[k]);
            float2 f_3 = __half22float2(p3[k]);
            a[2*k]   += f_1.x + f_2.x + f_3.x;
            a[2*k+1] += f_1.y + f_2.y + f_3.y;
        }
    }
    {
        const float4* p = (const float4*)item_emb + (size_t)it * D4;
        float4 f0 = p[lane * 2], f1 = p[lane * 2 + 1];
        b[0] = f0.x; b[1] = f0.y; b[2] = f0.z; b[3] = f0.w;
        b[4] = f1.x; b[5] = f1.y; b[6] = f1.z; b[7] = f1.w;
        uint4 q1 = h1v[in_ * DH4 + lane];
        uint4 q2 = h2v[in_ * DH4 + lane];
        uint4 q3 = h3v[(size_t)(w + BATCH) * DH4 + lane];
        const __half2 *p1 = (const __half2*)&q1, *p2 = (const __half2*)&q2, *p3 = (const __half2*)&q3;
#pragma unroll
        for (int k = 0; k < 4; k++) {
            float2 f_1 = __half22float2(p1[k]);
            float2 f_2 = __half22float2(p2[k]);
            float2 f_3 = __half22float2(p3[k]);
            b[2*k]   += f_1.x + f_2.x + f_3.x;
            b[2*k+1] += f_1.y + f_2.y + f_3.y;
        }
    }

    float acc = 0.f;
#pragma unroll
    for (int k = 0; k < 8; k++) acc += a[k] * b[k];

#pragma unroll
    for (int off = 16; off > 0; off >>= 1)
        acc += __shfl_down_sync(0xFFFFFFFFu, acc, off);

    if (lane == 0) out[w] = acc * (1.0f / 16.0f);   // (1/4)*(1/4)
}

extern "C" void kernel_launch(void* const* d_in, const int* in_sizes, int n_in,
                              void* d_out, int out_size) {
    const float* user_emb = (const float*)d_in[0];
    const float* item_emb = (const float*)d_in[1];
    const float* vals     = (const float*)d_in[2];
    const int*   rows     = (const int*)d_in[3];
    const int*   cols     = (const int*)d_in[4];
    const int*   users    = (const int*)d_in[5];
    const int*   items    = (const int*)d_in[6];
    float* out = (float*)d_out;

    __half *h0, *h1, *h2, *h3c;
    int *counts, *local, *blocksums, *rowptr, *fill;
    int2 *edges;
    cudaGetSymbolAddress((void**)&h0, g_h0);
    cudaGetSymbolAddress((void**)&h1, g_h1);
    cudaGetSymbolAddress((void**)&h2, g_h2);
    cudaGetSymbolAddress((void**)&h3c, g_h3c);
    cudaGetSymbolAddress((void**)&counts, g_counts);
    cudaGetSymbolAddress((void**)&local, g_local);
    cudaGetSymbolAddress((void**)&blocksums, g_blocksums);
    cudaGetSymbolAddress((void**)&rowptr, g_rowptr);
    cudaGetSymbolAddress((void**)&fill, g_fill);
    cudaGetSymbolAddress((void**)&edges, g_edges);

    // ---- fused zero + fp16 convert ----
    zero_and_tohalf_kernel<<<(N_NODES * D4 + 255) / 256, 256>>>(
        user_emb, item_emb, h0, counts);

    // ---- histogram (8 edges/thread) ----
    hist_kernel<<<(NNZ / 8 + 255) / 256, 256>>>((const int4*)rows, counts);

    // ---- 2-kernel coalesced scan ----
    scan_local_kernel<<<SCAN_NBLK, SCAN_BLOCK>>>(counts, local, blocksums);
    scan_add_kernel<<<SCAN_NBLK, SCAN_BLOCK>>>(local, blocksums, rowptr, fill);

    // ---- scatter (8 edges/thread) ----
    scatter_kernel<<<(NNZ / 8 + 255) / 256, 256>>>(
        (const int4*)rows, (const int4*)cols, (const float4*)vals, fill, edges);

    // ---- 2 full SpMM passes + restricted pass 3 ----
    const int spmm_blocks = (N_NODES * 32 + 255) / 256;
    spmm_csr_kernel<<<spmm_blocks, 256>>>(h0, rowptr, edges, h1);
    spmm_csr_kernel<<<spmm_blocks, 256>>>(h1, rowptr, edges, h2);
    spmm_batch_kernel<<<(2 * BATCH * 32 + 255) / 256, 256>>>(
        h2, rowptr, edges, users, items, h3c);

    // ---- final gather + dot ----
    gather_dot_kernel<<<(BATCH * 32 + 255) / 256, 256>>>(
        user_emb, item_emb, users, items, h1, h2, h3c, out);
}